// round 2
// baseline (speedup 1.0000x reference)
#include <cuda_runtime.h>
#include <cuda_bf16.h>
#include <math.h>

// Problem constants
#define T_LEN 2048
#define BATCH 2
#define EMBED 1024
#define NHEAD 16
#define HDIM  64
#define BHEAD (BATCH * NHEAD)          // 32
#define NTOK  (T_LEN * BATCH)          // 4096
#define SCALING 0.125f                  // 64^-0.5

// Scratch (allocation-free rule: __device__ globals)
__device__ float g_q[BHEAD * T_LEN * HDIM];     // [bh][t][d], pre-scaled
__device__ float g_k[BHEAD * T_LEN * HDIM];
__device__ float g_v[BHEAD * T_LEN * HDIM];
__device__ float g_ctx[NTOK * EMBED];           // [t*2+b][e] attention output

// ---------------------------------------------------------------------------
// Kernel 1: QKV projection.  C[n,f] = dot(x[n,:], W[f,:]) + bias[f]
// n in [0,4096), f in [0,3072).  Epilogue scatters to g_q/g_k/g_v with q scaling.
// 128x128 block tile, BK=8, 256 threads, 8x8 per thread (2x2 split of 4x4).
// ---------------------------------------------------------------------------
__global__ __launch_bounds__(256) void qkv_kernel(
    const float* __restrict__ x,      // [4096,1024]
    const float* __restrict__ w,      // [3072,1024]
    const float* __restrict__ bias)   // [3072]
{
    __shared__ float As[8][128];   // [k][m]
    __shared__ float Bs[8][128];   // [k][n]

    const int bm = blockIdx.y * 128;
    const int bn = blockIdx.x * 128;
    const int tid = threadIdx.x;
    const int tx = tid & 15;       // 0..15 -> n
    const int ty = tid >> 4;       // 0..15 -> m

    float acc[2][2][4][4];
    #pragma unroll
    for (int a = 0; a < 2; a++)
        #pragma unroll
        for (int b = 0; b < 2; b++)
            #pragma unroll
            for (int i = 0; i < 4; i++)
                #pragma unroll
                for (int j = 0; j < 4; j++) acc[a][b][i][j] = 0.f;

    const int lr = tid >> 1;            // 0..127 row within tile
    const int lc = (tid & 1) * 4;       // 0 or 4
    const float* aptr = x + (size_t)(bm + lr) * EMBED + lc;
    const float* bptr = w + (size_t)(bn + lr) * EMBED + lc;

    for (int k0 = 0; k0 < EMBED; k0 += 8) {
        float4 av = *(const float4*)(aptr + k0);
        float4 bv = *(const float4*)(bptr + k0);
        As[lc + 0][lr] = av.x; As[lc + 1][lr] = av.y;
        As[lc + 2][lr] = av.z; As[lc + 3][lr] = av.w;
        Bs[lc + 0][lr] = bv.x; Bs[lc + 1][lr] = bv.y;
        Bs[lc + 2][lr] = bv.z; Bs[lc + 3][lr] = bv.w;
        __syncthreads();
        #pragma unroll
        for (int kk = 0; kk < 8; kk++) {
            float4 a0 = *(const float4*)&As[kk][ty * 4];
            float4 a1 = *(const float4*)&As[kk][ty * 4 + 64];
            float4 b0 = *(const float4*)&Bs[kk][tx * 4];
            float4 b1 = *(const float4*)&Bs[kk][tx * 4 + 64];
            float ar[2][4] = {{a0.x, a0.y, a0.z, a0.w}, {a1.x, a1.y, a1.z, a1.w}};
            float br[2][4] = {{b0.x, b0.y, b0.z, b0.w}, {b1.x, b1.y, b1.z, b1.w}};
            #pragma unroll
            for (int im = 0; im < 2; im++)
                #pragma unroll
                for (int in2 = 0; in2 < 2; in2++)
                    #pragma unroll
                    for (int i = 0; i < 4; i++)
                        #pragma unroll
                        for (int j = 0; j < 4; j++)
                            acc[im][in2][i][j] = fmaf(ar[im][i], br[in2][j], acc[im][in2][i][j]);
        }
        __syncthreads();
    }

    // Epilogue: bias, q-scaling, scatter to [bh][t][d]
    #pragma unroll
    for (int im = 0; im < 2; im++) {
        #pragma unroll
        for (int i = 0; i < 4; i++) {
            int m = bm + im * 64 + ty * 4 + i;        // token row
            int t = m >> 1;
            int b = m & 1;
            #pragma unroll
            for (int in2 = 0; in2 < 2; in2++) {
                #pragma unroll
                for (int j = 0; j < 4; j++) {
                    int f = bn + in2 * 64 + tx * 4 + j;
                    float c = acc[im][in2][i][j] + bias[f];
                    int which = f >> 10;        // 0=q,1=k,2=v
                    int hd = f & 1023;
                    int h = hd >> 6;
                    int d = hd & 63;
                    if (which == 0) c *= SCALING;
                    float* dst = (which == 0) ? g_q : (which == 1) ? g_k : g_v;
                    dst[(((size_t)(b * NHEAD + h)) * T_LEN + t) * HDIM + d] = c;
                }
            }
        }
    }
}

// ---------------------------------------------------------------------------
// Kernel 2: flash attention, fp32.  One block = (bh, 64-query tile).
// Smem layouts chosen so all inner-loop reads are conflict-free LDS.128:
//   Qs[k][r], Ks[k][c], Vs[s][d], Ps[c][r]  (all padded to 68 floats/row)
// ---------------------------------------------------------------------------
#define PADW 68
#define ATTN_SMEM ((4 * 64 * PADW + 3 * 64) * (int)sizeof(float))

__global__ __launch_bounds__(256) void attn_kernel()
{
    extern __shared__ float sm[];
    float* Qs = sm;                    // [64][68] transposed: [k][r]
    float* Ks = Qs + 64 * PADW;        // [64][68] transposed: [k][c]
    float* Vs = Ks + 64 * PADW;        // [64][68] natural:    [s][d]
    float* Ps = Vs + 64 * PADW;        // [64][68] transposed: [c][r]
    float* sm_m = Ps + 64 * PADW;      // [64] running row max
    float* sm_a = sm_m + 64;           // [64] rescale alpha
    float* sm_l = sm_a + 64;           // [64] 1/l at end

    const int bh = blockIdx.y;
    const int q0 = blockIdx.x * 64;
    const int tid = threadIdx.x;
    const int tx = tid & 15;           // -> col group (keys / dims)
    const int ty = tid >> 4;           // -> row group (queries)

    const float* qptr = g_q + (size_t)bh * T_LEN * HDIM;
    const float* kptr = g_k + (size_t)bh * T_LEN * HDIM;
    const float* vptr = g_v + (size_t)bh * T_LEN * HDIM;

    // Load Q tile transposed
    #pragma unroll
    for (int it = 0; it < 4; it++) {
        int idx = tid + it * 256;      // float4 index, 1024 total
        int r = idx >> 4;
        int c4 = (idx & 15) * 4;
        float4 qv = *(const float4*)(qptr + (size_t)(q0 + r) * HDIM + c4);
        Qs[(c4 + 0) * PADW + r] = qv.x;
        Qs[(c4 + 1) * PADW + r] = qv.y;
        Qs[(c4 + 2) * PADW + r] = qv.z;
        Qs[(c4 + 3) * PADW + r] = qv.w;
    }

    float m_i = -1e30f, l_i = 0.f;     // valid for tid<64 (row = tid)
    float accO[4][4];
    #pragma unroll
    for (int i = 0; i < 4; i++)
        #pragma unroll
        for (int j = 0; j < 4; j++) accO[i][j] = 0.f;

    for (int s0 = 0; s0 < T_LEN; s0 += 64) {
        // Load K (transposed) and V (natural)
        #pragma unroll
        for (int it = 0; it < 4; it++) {
            int idx = tid + it * 256;
            int r = idx >> 4;
            int c4 = (idx & 15) * 4;
            float4 kv = *(const float4*)(kptr + (size_t)(s0 + r) * HDIM + c4);
            Ks[(c4 + 0) * PADW + r] = kv.x;
            Ks[(c4 + 1) * PADW + r] = kv.y;
            Ks[(c4 + 2) * PADW + r] = kv.z;
            Ks[(c4 + 3) * PADW + r] = kv.w;
            float4 vv = *(const float4*)(vptr + (size_t)(s0 + r) * HDIM + c4);
            *(float4*)(Vs + r * PADW + c4) = vv;
        }
        __syncthreads();

        // S = Q K^T  (thread owns rows ty*4+i, cols tx*4+j)
        float accS[4][4];
        #pragma unroll
        for (int i = 0; i < 4; i++)
            #pragma unroll
            for (int j = 0; j < 4; j++) accS[i][j] = 0.f;
        #pragma unroll 8
        for (int kk = 0; kk < 64; kk++) {
            float4 qa = *(const float4*)(Qs + kk * PADW + ty * 4);
            float4 kb = *(const float4*)(Ks + kk * PADW + tx * 4);
            float qr[4] = {qa.x, qa.y, qa.z, qa.w};
            float kr[4] = {kb.x, kb.y, kb.z, kb.w};
            #pragma unroll
            for (int i = 0; i < 4; i++)
                #pragma unroll
                for (int j = 0; j < 4; j++)
                    accS[i][j] = fmaf(qr[i], kr[j], accS[i][j]);
        }

        // Stage raw S (transposed) for row-max
        #pragma unroll
        for (int i = 0; i < 4; i++)
            #pragma unroll
            for (int j = 0; j < 4; j++)
                Ps[(tx * 4 + j) * PADW + (ty * 4 + i)] = accS[i][j];
        __syncthreads();

        if (tid < 64) {
            float mx = -1e30f;
            #pragma unroll 8
            for (int c = 0; c < 64; c++) mx = fmaxf(mx, Ps[c * PADW + tid]);
            float m_new = fmaxf(m_i, mx);
            sm_a[tid] = __expf(m_i - m_new);
            sm_m[tid] = m_new;
            m_i = m_new;
        }
        __syncthreads();

        // exp + O rescale (uses register copy of S)
        float alpha[4], mrow[4];
        #pragma unroll
        for (int i = 0; i < 4; i++) { alpha[i] = sm_a[ty * 4 + i]; mrow[i] = sm_m[ty * 4 + i]; }
        #pragma unroll
        for (int i = 0; i < 4; i++)
            #pragma unroll
            for (int j = 0; j < 4; j++) {
                float p = __expf(accS[i][j] - mrow[i]);
                Ps[(tx * 4 + j) * PADW + (ty * 4 + i)] = p;
                accO[i][j] *= alpha[i];
            }
        __syncthreads();

        // row-sum for l (tid<64) — concurrent with PV (both only read Ps)
        if (tid < 64) {
            float s = 0.f;
            #pragma unroll 8
            for (int c = 0; c < 64; c++) s += Ps[c * PADW + tid];
            l_i = l_i * sm_a[tid] + s;
        }

        // O += P V   (Ps is [s][r] transposed, Vs is [s][d])
        #pragma unroll 8
        for (int ss = 0; ss < 64; ss++) {
            float4 pa = *(const float4*)(Ps + ss * PADW + ty * 4);
            float4 vb = *(const float4*)(Vs + ss * PADW + tx * 4);
            float pr[4] = {pa.x, pa.y, pa.z, pa.w};
            float vr[4] = {vb.x, vb.y, vb.z, vb.w};
            #pragma unroll
            for (int i = 0; i < 4; i++)
                #pragma unroll
                for (int j = 0; j < 4; j++)
                    accO[i][j] = fmaf(pr[i], vr[j], accO[i][j]);
        }
        __syncthreads();   // protect smem before next tile load
    }

    if (tid < 64) sm_l[tid] = 1.0f / l_i;
    __syncthreads();

    // Write ctx[t*2+b][h*64+d]
    const int b = bh >> 4;
    const int h = bh & 15;
    #pragma unroll
    for (int i = 0; i < 4; i++) {
        int t = q0 + ty * 4 + i;
        float inv = sm_l[ty * 4 + i];
        float4 o;
        o.x = accO[i][0] * inv;
        o.y = accO[i][1] * inv;
        o.z = accO[i][2] * inv;
        o.w = accO[i][3] * inv;
        *(float4*)(g_ctx + ((size_t)t * BATCH + b) * EMBED + h * HDIM + tx * 4) = o;
    }
}

// ---------------------------------------------------------------------------
// Kernel 3: output projection.  out[n,f] = dot(ctx[n,:], Wo[f,:]) + bias[f]
// Same sgemm core as kernel 1.
// ---------------------------------------------------------------------------
__global__ __launch_bounds__(256) void outproj_kernel(
    const float* __restrict__ w,      // [1024,1024]
    const float* __restrict__ bias,   // [1024]
    float* __restrict__ out)          // [4096,1024]
{
    __shared__ float As[8][128];
    __shared__ float Bs[8][128];

    const int bm = blockIdx.y * 128;
    const int bn = blockIdx.x * 128;
    const int tid = threadIdx.x;
    const int tx = tid & 15;
    const int ty = tid >> 4;

    float acc[2][2][4][4];
    #pragma unroll
    for (int a = 0; a < 2; a++)
        #pragma unroll
        for (int b = 0; b < 2; b++)
            #pragma unroll
            for (int i = 0; i < 4; i++)
                #pragma unroll
                for (int j = 0; j < 4; j++) acc[a][b][i][j] = 0.f;

    const int lr = tid >> 1;
    const int lc = (tid & 1) * 4;
    const float* aptr = g_ctx + (size_t)(bm + lr) * EMBED + lc;
    const float* bptr = w + (size_t)(bn + lr) * EMBED + lc;

    for (int k0 = 0; k0 < EMBED; k0 += 8) {
        float4 av = *(const float4*)(aptr + k0);
        float4 bv = *(const float4*)(bptr + k0);
        As[lc + 0][lr] = av.x; As[lc + 1][lr] = av.y;
        As[lc + 2][lr] = av.z; As[lc + 3][lr] = av.w;
        Bs[lc + 0][lr] = bv.x; Bs[lc + 1][lr] = bv.y;
        Bs[lc + 2][lr] = bv.z; Bs[lc + 3][lr] = bv.w;
        __syncthreads();
        #pragma unroll
        for (int kk = 0; kk < 8; kk++) {
            float4 a0 = *(const float4*)&As[kk][ty * 4];
            float4 a1 = *(const float4*)&As[kk][ty * 4 + 64];
            float4 b0 = *(const float4*)&Bs[kk][tx * 4];
            float4 b1 = *(const float4*)&Bs[kk][tx * 4 + 64];
            float ar[2][4] = {{a0.x, a0.y, a0.z, a0.w}, {a1.x, a1.y, a1.z, a1.w}};
            float br[2][4] = {{b0.x, b0.y, b0.z, b0.w}, {b1.x, b1.y, b1.z, b1.w}};
            #pragma unroll
            for (int im = 0; im < 2; im++)
                #pragma unroll
                for (int in2 = 0; in2 < 2; in2++)
                    #pragma unroll
                    for (int i = 0; i < 4; i++)
                        #pragma unroll
                        for (int j = 0; j < 4; j++)
                            acc[im][in2][i][j] = fmaf(ar[im][i], br[in2][j], acc[im][in2][i][j]);
        }
        __syncthreads();
    }

    #pragma unroll
    for (int im = 0; im < 2; im++)
        #pragma unroll
        for (int i = 0; i < 4; i++) {
            int m = bm + im * 64 + ty * 4 + i;
            #pragma unroll
            for (int in2 = 0; in2 < 2; in2++)
                #pragma unroll
                for (int j = 0; j < 4; j++) {
                    int f = bn + in2 * 64 + tx * 4 + j;
                    out[(size_t)m * EMBED + f] = acc[im][in2][i][j] + bias[f];
                }
        }
}

// ---------------------------------------------------------------------------
extern "C" void kernel_launch(void* const* d_in, const int* in_sizes, int n_in,
                              void* d_out, int out_size)
{
    const float* x  = (const float*)d_in[0];   // [2048,2,1024]
    const float* w1 = (const float*)d_in[1];   // [3072,1024]
    const float* b1 = (const float*)d_in[2];   // [3072]
    const float* w2 = (const float*)d_in[3];   // [1024,1024]
    const float* b2 = (const float*)d_in[4];   // [1024]
    float* out = (float*)d_out;

    static bool attr_set = false;
    if (!attr_set) {
        cudaFuncSetAttribute(attn_kernel,
                             cudaFuncAttributeMaxDynamicSharedMemorySize, ATTN_SMEM);
        attr_set = true;
    }

    qkv_kernel<<<dim3(24, 32), 256>>>(x, w1, b1);
    attn_kernel<<<dim3(T_LEN / 64, BHEAD), 256, ATTN_SMEM>>>();
    outproj_kernel<<<dim3(8, 32), 256>>>(w2, b2, out);
}

// round 3
// speedup vs baseline: 3.9030x; 3.9030x over previous
#include <cuda_runtime.h>
#include <cuda_bf16.h>
#include <cstdint>

// Problem constants
#define T_LEN 2048
#define BATCH 2
#define EMBED 1024
#define NHEAD 16
#define HDIM  64
#define BHEAD (BATCH * NHEAD)          // 32
#define NTOK  (T_LEN * BATCH)          // 4096
// 0.125 (=64^-0.5) * log2(e): softmax computed in base-2 domain
#define QSCALE 0.18033688011112042f

// Scratch (allocation-free rule: __device__ globals)
__device__ float g_q[BHEAD * T_LEN * HDIM];     // [bh][t][d], pre-scaled by QSCALE
__device__ float g_k[BHEAD * T_LEN * HDIM];
__device__ float g_v[BHEAD * T_LEN * HDIM];
__device__ float g_ctx[NTOK * EMBED];           // [t*2+b][e]

// ---------------------------------------------------------------------------
// PTX helpers
// ---------------------------------------------------------------------------
__device__ __forceinline__ uint32_t s2u(const void* p) {
    return (uint32_t)__cvta_generic_to_shared(p);
}
__device__ __forceinline__ uint32_t f2tf(float x) {
    uint32_t r; asm("cvt.rna.tf32.f32 %0, %1;" : "=r"(r) : "f"(x)); return r;
}
__device__ __forceinline__ float ex2f(float x) {
    float r; asm("ex2.approx.f32 %0, %1;" : "=f"(r) : "f"(x)); return r;
}
__device__ __forceinline__ void ldsm4(uint32_t& r0, uint32_t& r1, uint32_t& r2,
                                      uint32_t& r3, uint32_t addr) {
    asm volatile("ldmatrix.sync.aligned.m8n8.x4.shared.b16 {%0,%1,%2,%3}, [%4];"
                 : "=r"(r0), "=r"(r1), "=r"(r2), "=r"(r3) : "r"(addr));
}
__device__ __forceinline__ void mma8(float* c, const uint32_t* a, const uint32_t* b) {
    asm volatile(
        "mma.sync.aligned.m16n8k8.row.col.f32.tf32.tf32.f32 "
        "{%0,%1,%2,%3}, {%4,%5,%6,%7}, {%8,%9}, {%0,%1,%2,%3};\n"
        : "+f"(c[0]), "+f"(c[1]), "+f"(c[2]), "+f"(c[3])
        : "r"(a[0]), "r"(a[1]), "r"(a[2]), "r"(a[3]), "r"(b[0]), "r"(b[1]));
}

// ---------------------------------------------------------------------------
// Kernel 1: QKV projection (tf32 tensor core).
// C[m,f] = dot(x[m,:], W[f,:]) + bias[f];  m<4096, f<3072.
// Block 128x128, BK=32, 256 threads = 8 warps, warp tile 64x32.
// Smem rows k-major, stride 36 floats -> conflict-free ldmatrix + STS.
// ---------------------------------------------------------------------------
#define GST 36

__global__ __launch_bounds__(256) void qkv_kernel(
    const float* __restrict__ x,      // [4096,1024]
    const float* __restrict__ w,      // [3072,1024]
    const float* __restrict__ bias)   // [3072]
{
    __shared__ __align__(16) uint32_t As[128 * GST];
    __shared__ __align__(16) uint32_t Bs[128 * GST];

    const int bm = blockIdx.y * 128, bn = blockIdx.x * 128;
    const int tid = threadIdx.x, wid = tid >> 5, lane = tid & 31;
    const int gr = lane >> 2, tig = lane & 3;
    const int wm = (wid & 1) * 64, wn = (wid >> 1) * 32;
    const int r0 = tid >> 3, q = tid & 7;

    float acc[4][4][4];
    #pragma unroll
    for (int i = 0; i < 4; i++)
        #pragma unroll
        for (int j = 0; j < 4; j++)
            #pragma unroll
            for (int r = 0; r < 4; r++) acc[i][j][r] = 0.f;

    const float* ap = x + (size_t)(bm + r0) * EMBED + q * 4;
    const float* bp = w + (size_t)(bn + r0) * EMBED + q * 4;

    float4 pa[4], pb[4];
    #pragma unroll
    for (int it = 0; it < 4; it++) {
        pa[it] = *(const float4*)(ap + (size_t)it * 32 * EMBED);
        pb[it] = *(const float4*)(bp + (size_t)it * 32 * EMBED);
    }
    #pragma unroll
    for (int it = 0; it < 4; it++) {
        *(uint4*)(As + (r0 + 32 * it) * GST + q * 4) =
            make_uint4(f2tf(pa[it].x), f2tf(pa[it].y), f2tf(pa[it].z), f2tf(pa[it].w));
        *(uint4*)(Bs + (r0 + 32 * it) * GST + q * 4) =
            make_uint4(f2tf(pb[it].x), f2tf(pb[it].y), f2tf(pb[it].z), f2tf(pb[it].w));
    }
    __syncthreads();

    const uint32_t as_base = s2u(As), bs_base = s2u(Bs);

    #pragma unroll 1
    for (int kb = 0; kb < 32; kb++) {
        if (kb < 31) {
            int k0 = (kb + 1) * 32;
            #pragma unroll
            for (int it = 0; it < 4; it++) {
                pa[it] = *(const float4*)(ap + (size_t)it * 32 * EMBED + k0);
                pb[it] = *(const float4*)(bp + (size_t)it * 32 * EMBED + k0);
            }
        }
        #pragma unroll
        for (int ks = 0; ks < 4; ks++) {
            int k8 = ks * 8;
            uint32_t bfr[4][2];
            #pragma unroll
            for (int p = 0; p < 2; p++) {
                int row = wn + 16 * p + (lane & 7) + ((lane >> 4) << 3);
                int col = k8 + 4 * ((lane >> 3) & 1);
                ldsm4(bfr[2 * p][0], bfr[2 * p][1], bfr[2 * p + 1][0], bfr[2 * p + 1][1],
                      bs_base + (row * GST + col) * 4);
            }
            #pragma unroll
            for (int mi = 0; mi < 4; mi++) {
                uint32_t a[4];
                int row = wm + 16 * mi + (lane & 15);
                int col = k8 + 4 * (lane >> 4);
                ldsm4(a[0], a[1], a[2], a[3], as_base + (row * GST + col) * 4);
                #pragma unroll
                for (int nj = 0; nj < 4; nj++) mma8(acc[mi][nj], a, bfr[nj]);
            }
        }
        __syncthreads();
        if (kb < 31) {
            #pragma unroll
            for (int it = 0; it < 4; it++) {
                *(uint4*)(As + (r0 + 32 * it) * GST + q * 4) =
                    make_uint4(f2tf(pa[it].x), f2tf(pa[it].y), f2tf(pa[it].z), f2tf(pa[it].w));
                *(uint4*)(Bs + (r0 + 32 * it) * GST + q * 4) =
                    make_uint4(f2tf(pb[it].x), f2tf(pb[it].y), f2tf(pb[it].z), f2tf(pb[it].w));
            }
            __syncthreads();
        }
    }

    // Epilogue: bias, q-scaling (with log2e folded in), scatter to [bh][t][d]
    #pragma unroll
    for (int mi = 0; mi < 4; mi++)
        #pragma unroll
        for (int nj = 0; nj < 4; nj++)
            #pragma unroll
            for (int rr = 0; rr < 2; rr++) {
                int m = bm + wm + mi * 16 + gr + 8 * rr;
                int f = bn + wn + nj * 8 + 2 * tig;
                float c0 = acc[mi][nj][rr * 2 + 0] + bias[f];
                float c1 = acc[mi][nj][rr * 2 + 1] + bias[f + 1];
                int which = f >> 10, hd = f & 1023, h = hd >> 6, d = hd & 63;
                int t = m >> 1, bb = m & 1;
                if (which == 0) { c0 *= QSCALE; c1 *= QSCALE; }
                float* dst = (which == 0) ? g_q : (which == 1) ? g_k : g_v;
                *(float2*)(dst + (((size_t)(bb * NHEAD + h)) * T_LEN + t) * HDIM + d) =
                    make_float2(c0, c1);
            }
}

// ---------------------------------------------------------------------------
// Kernel 2: flash attention (tf32 tensor core).
// Block = (bh, 128-query tile), 4 warps; warp owns 32 q-rows x 64-key s-tile.
// Smem (tf32 bits): Qs[128][68], Ks[64][68] ([s][d]), Vs[64][68] ([d][s]),
// Ps[128][68] ([q][s], warp-private rows).  Softmax in base-2.
// ---------------------------------------------------------------------------
#define AST 68
#define ATTN_SMEM ((128 + 64 + 64 + 128) * AST * 4)

__global__ __launch_bounds__(128) void attn_kernel()
{
    extern __shared__ uint32_t sm[];
    uint32_t* Qs = sm;                    // [128][68]
    uint32_t* Ks = Qs + 128 * AST;        // [64][68]
    uint32_t* Vs = Ks + 64 * AST;         // [64][68] transposed [d][s]
    uint32_t* Ps = Vs + 64 * AST;         // [128][68]

    const int bh = blockIdx.y;
    const int q0 = blockIdx.x * 128;
    const int tid = threadIdx.x, wid = tid >> 5, lane = tid & 31;
    const int gr = lane >> 2, tig = lane & 3;
    const int warp_q = wid * 32;

    const float* qg = g_q + (size_t)bh * T_LEN * HDIM;
    const float* kg = g_k + (size_t)bh * T_LEN * HDIM;
    const float* vg = g_v + (size_t)bh * T_LEN * HDIM;

    // Load Q tile (128x64) into smem, tf32
    {
        int r0 = tid >> 4, c4 = (tid & 15) * 4;
        #pragma unroll
        for (int i = 0; i < 16; i++) {
            int r = r0 + 8 * i;
            float4 v = *(const float4*)(qg + (size_t)(q0 + r) * HDIM + c4);
            *(uint4*)(Qs + r * AST + c4) =
                make_uint4(f2tf(v.x), f2tf(v.y), f2tf(v.z), f2tf(v.w));
        }
    }

    float accO[2][8][4];
    #pragma unroll
    for (int mi = 0; mi < 2; mi++)
        #pragma unroll
        for (int nf = 0; nf < 8; nf++)
            #pragma unroll
            for (int r = 0; r < 4; r++) accO[mi][nf][r] = 0.f;
    float m_s[2][2] = {{-1e30f, -1e30f}, {-1e30f, -1e30f}};
    float l_s[2][2] = {{0.f, 0.f}, {0.f, 0.f}};

    const uint32_t qs_base = s2u(Qs), ks_base = s2u(Ks),
                   vs_base = s2u(Vs), ps_base = s2u(Ps);

    #pragma unroll 1
    for (int s0 = 0; s0 < T_LEN; s0 += 64) {
        // Load K (natural [s][d]) and V (transposed [d][s])
        {
            int r0 = tid >> 4, c4 = (tid & 15) * 4;
            #pragma unroll
            for (int i = 0; i < 8; i++) {
                int r = r0 + 8 * i;
                float4 v = *(const float4*)(kg + (size_t)(s0 + r) * HDIM + c4);
                *(uint4*)(Ks + r * AST + c4) =
                    make_uint4(f2tf(v.x), f2tf(v.y), f2tf(v.z), f2tf(v.w));
            }
            int sv0 = tid >> 2, dv4 = (tid & 3) * 4;
            #pragma unroll
            for (int j = 0; j < 2; j++)
                #pragma unroll
                for (int i = 0; i < 4; i++) {
                    int s = sv0 + 32 * j, d4 = dv4 + 16 * i;
                    float4 v = *(const float4*)(vg + (size_t)(s0 + s) * HDIM + d4);
                    Vs[(d4 + 0) * AST + s] = f2tf(v.x);
                    Vs[(d4 + 1) * AST + s] = f2tf(v.y);
                    Vs[(d4 + 2) * AST + s] = f2tf(v.z);
                    Vs[(d4 + 3) * AST + s] = f2tf(v.w);
                }
        }
        __syncthreads();

        // S = Q K^T  (warp: 32 q-rows x 64 keys)
        float sfr[2][8][4];
        #pragma unroll
        for (int mi = 0; mi < 2; mi++)
            #pragma unroll
            for (int nf = 0; nf < 8; nf++)
                #pragma unroll
                for (int r = 0; r < 4; r++) sfr[mi][nf][r] = 0.f;

        #pragma unroll
        for (int ks = 0; ks < 8; ks++) {
            int k8 = ks * 8;
            uint32_t kb[8][2];
            #pragma unroll
            for (int p = 0; p < 4; p++) {
                int row = 16 * p + (lane & 7) + ((lane >> 4) << 3);
                int col = k8 + 4 * ((lane >> 3) & 1);
                ldsm4(kb[2 * p][0], kb[2 * p][1], kb[2 * p + 1][0], kb[2 * p + 1][1],
                      ks_base + (row * AST + col) * 4);
            }
            #pragma unroll
            for (int mi = 0; mi < 2; mi++) {
                uint32_t a[4];
                int row = warp_q + mi * 16 + (lane & 15);
                int col = k8 + 4 * (lane >> 4);
                ldsm4(a[0], a[1], a[2], a[3], qs_base + (row * AST + col) * 4);
                #pragma unroll
                for (int nf = 0; nf < 8; nf++) mma8(sfr[mi][nf], a, kb[nf]);
            }
        }

        // Online softmax (base-2 domain); row owned by 4 lanes (same gr)
        #pragma unroll
        for (int mi = 0; mi < 2; mi++)
            #pragma unroll
            for (int rr = 0; rr < 2; rr++) {
                float mx = -1e30f;
                #pragma unroll
                for (int nf = 0; nf < 8; nf++)
                    mx = fmaxf(mx, fmaxf(sfr[mi][nf][rr * 2], sfr[mi][nf][rr * 2 + 1]));
                mx = fmaxf(mx, __shfl_xor_sync(0xffffffffu, mx, 1));
                mx = fmaxf(mx, __shfl_xor_sync(0xffffffffu, mx, 2));
                float mn = fmaxf(m_s[mi][rr], mx);
                float al = ex2f(m_s[mi][rr] - mn);
                m_s[mi][rr] = mn;
                float rs = 0.f;
                #pragma unroll
                for (int nf = 0; nf < 8; nf++) {
                    float p0 = ex2f(sfr[mi][nf][rr * 2] - mn);
                    float p1 = ex2f(sfr[mi][nf][rr * 2 + 1] - mn);
                    sfr[mi][nf][rr * 2] = p0;
                    sfr[mi][nf][rr * 2 + 1] = p1;
                    rs += p0 + p1;
                    accO[mi][nf][rr * 2] *= al;
                    accO[mi][nf][rr * 2 + 1] *= al;
                }
                rs += __shfl_xor_sync(0xffffffffu, rs, 1);
                rs += __shfl_xor_sync(0xffffffffu, rs, 2);
                l_s[mi][rr] = l_s[mi][rr] * al + rs;
            }

        // Store P (tf32) to warp-private Ps rows
        #pragma unroll
        for (int mi = 0; mi < 2; mi++)
            #pragma unroll
            for (int nf = 0; nf < 8; nf++) {
                int col = nf * 8 + 2 * tig;
                int rw = warp_q + mi * 16 + gr;
                *(uint2*)(Ps + rw * AST + col) =
                    make_uint2(f2tf(sfr[mi][nf][0]), f2tf(sfr[mi][nf][1]));
                *(uint2*)(Ps + (rw + 8) * AST + col) =
                    make_uint2(f2tf(sfr[mi][nf][2]), f2tf(sfr[mi][nf][3]));
            }
    __syncwarp();

        // O += P V   (A = P[q][s], B = Vs[d][s])
        #pragma unroll
        for (int ks = 0; ks < 8; ks++) {
            int s8 = ks * 8;
            uint32_t vb[8][2];
            #pragma unroll
            for (int p = 0; p < 4; p++) {
                int row = 16 * p + (lane & 7) + ((lane >> 4) << 3);
                int col = s8 + 4 * ((lane >> 3) & 1);
                ldsm4(vb[2 * p][0], vb[2 * p][1], vb[2 * p + 1][0], vb[2 * p + 1][1],
                      vs_base + (row * AST + col) * 4);
            }
            #pragma unroll
            for (int mi = 0; mi < 2; mi++) {
                uint32_t a[4];
                int row = warp_q + mi * 16 + (lane & 15);
                int col = s8 + 4 * (lane >> 4);
                ldsm4(a[0], a[1], a[2], a[3], ps_base + (row * AST + col) * 4);
                #pragma unroll
                for (int nf = 0; nf < 8; nf++) mma8(accO[mi][nf], a, vb[nf]);
            }
        }
        __syncthreads();   // protect Ks/Vs before next tile load
    }

    // Normalize and write ctx[t*2+b][h*64+d]
    const int bb = bh >> 4;
    const int h = bh & 15;
    #pragma unroll
    for (int mi = 0; mi < 2; mi++)
        #pragma unroll
        for (int rr = 0; rr < 2; rr++) {
            float inv = 1.0f / l_s[mi][rr];
            int t = q0 + warp_q + mi * 16 + gr + 8 * rr;
            #pragma unroll
            for (int nf = 0; nf < 8; nf++) {
                int d = nf * 8 + 2 * tig;
                *(float2*)(g_ctx + ((size_t)t * BATCH + bb) * EMBED + h * HDIM + d) =
                    make_float2(accO[mi][nf][rr * 2] * inv,
                                accO[mi][nf][rr * 2 + 1] * inv);
            }
        }
}

// ---------------------------------------------------------------------------
// Kernel 3: output projection (tf32 tensor core).  Same core as kernel 1.
// ---------------------------------------------------------------------------
__global__ __launch_bounds__(256) void outproj_kernel(
    const float* __restrict__ w,      // [1024,1024]
    const float* __restrict__ bias,   // [1024]
    float* __restrict__ out)          // [4096,1024]
{
    __shared__ __align__(16) uint32_t As[128 * GST];
    __shared__ __align__(16) uint32_t Bs[128 * GST];

    const int bm = blockIdx.y * 128, bn = blockIdx.x * 128;
    const int tid = threadIdx.x, wid = tid >> 5, lane = tid & 31;
    const int gr = lane >> 2, tig = lane & 3;
    const int wm = (wid & 1) * 64, wn = (wid >> 1) * 32;
    const int r0 = tid >> 3, q = tid & 7;

    float acc[4][4][4];
    #pragma unroll
    for (int i = 0; i < 4; i++)
        #pragma unroll
        for (int j = 0; j < 4; j++)
            #pragma unroll
            for (int r = 0; r < 4; r++) acc[i][j][r] = 0.f;

    const float* ap = g_ctx + (size_t)(bm + r0) * EMBED + q * 4;
    const float* bp = w + (size_t)(bn + r0) * EMBED + q * 4;

    float4 pa[4], pb[4];
    #pragma unroll
    for (int it = 0; it < 4; it++) {
        pa[it] = *(const float4*)(ap + (size_t)it * 32 * EMBED);
        pb[it] = *(const float4*)(bp + (size_t)it * 32 * EMBED);
    }
    #pragma unroll
    for (int it = 0; it < 4; it++) {
        *(uint4*)(As + (r0 + 32 * it) * GST + q * 4) =
            make_uint4(f2tf(pa[it].x), f2tf(pa[it].y), f2tf(pa[it].z), f2tf(pa[it].w));
        *(uint4*)(Bs + (r0 + 32 * it) * GST + q * 4) =
            make_uint4(f2tf(pb[it].x), f2tf(pb[it].y), f2tf(pb[it].z), f2tf(pb[it].w));
    }
    __syncthreads();

    const uint32_t as_base = s2u(As), bs_base = s2u(Bs);

    #pragma unroll 1
    for (int kb = 0; kb < 32; kb++) {
        if (kb < 31) {
            int k0 = (kb + 1) * 32;
            #pragma unroll
            for (int it = 0; it < 4; it++) {
                pa[it] = *(const float4*)(ap + (size_t)it * 32 * EMBED + k0);
                pb[it] = *(const float4*)(bp + (size_t)it * 32 * EMBED + k0);
            }
        }
        #pragma unroll
        for (int ks = 0; ks < 4; ks++) {
            int k8 = ks * 8;
            uint32_t bfr[4][2];
            #pragma unroll
            for (int p = 0; p < 2; p++) {
                int row = wn + 16 * p + (lane & 7) + ((lane >> 4) << 3);
                int col = k8 + 4 * ((lane >> 3) & 1);
                ldsm4(bfr[2 * p][0], bfr[2 * p][1], bfr[2 * p + 1][0], bfr[2 * p + 1][1],
                      bs_base + (row * GST + col) * 4);
            }
            #pragma unroll
            for (int mi = 0; mi < 4; mi++) {
                uint32_t a[4];
                int row = wm + 16 * mi + (lane & 15);
                int col = k8 + 4 * (lane >> 4);
                ldsm4(a[0], a[1], a[2], a[3], as_base + (row * GST + col) * 4);
                #pragma unroll
                for (int nj = 0; nj < 4; nj++) mma8(acc[mi][nj], a, bfr[nj]);
            }
        }
        __syncthreads();
        if (kb < 31) {
            #pragma unroll
            for (int it = 0; it < 4; it++) {
                *(uint4*)(As + (r0 + 32 * it) * GST + q * 4) =
                    make_uint4(f2tf(pa[it].x), f2tf(pa[it].y), f2tf(pa[it].z), f2tf(pa[it].w));
                *(uint4*)(Bs + (r0 + 32 * it) * GST + q * 4) =
                    make_uint4(f2tf(pb[it].x), f2tf(pb[it].y), f2tf(pb[it].z), f2tf(pb[it].w));
            }
            __syncthreads();
        }
    }

    #pragma unroll
    for (int mi = 0; mi < 4; mi++)
        #pragma unroll
        for (int nj = 0; nj < 4; nj++)
            #pragma unroll
            for (int rr = 0; rr < 2; rr++) {
                int m = bm + wm + mi * 16 + gr + 8 * rr;
                int f = bn + wn + nj * 8 + 2 * tig;
                *(float2*)(out + (size_t)m * EMBED + f) =
                    make_float2(acc[mi][nj][rr * 2 + 0] + bias[f],
                                acc[mi][nj][rr * 2 + 1] + bias[f + 1]);
            }
}

// ---------------------------------------------------------------------------
extern "C" void kernel_launch(void* const* d_in, const int* in_sizes, int n_in,
                              void* d_out, int out_size)
{
    const float* x  = (const float*)d_in[0];   // [2048,2,1024]
    const float* w1 = (const float*)d_in[1];   // [3072,1024]
    const float* b1 = (const float*)d_in[2];   // [3072]
    const float* w2 = (const float*)d_in[3];   // [1024,1024]
    const float* b2 = (const float*)d_in[4];   // [1024]
    float* out = (float*)d_out;

    static bool attr_set = false;
    if (!attr_set) {
        cudaFuncSetAttribute(attn_kernel,
                             cudaFuncAttributeMaxDynamicSharedMemorySize, ATTN_SMEM);
        attr_set = true;
    }

    qkv_kernel<<<dim3(24, 32), 256>>>(x, w1, b1);
    attn_kernel<<<dim3(T_LEN / 128, BHEAD), 128, ATTN_SMEM>>>();
    outproj_kernel<<<dim3(8, 32), 256>>>(w2, b2, out);
}